// round 2
// baseline (speedup 1.0000x reference)
#include <cuda_runtime.h>
#include <math.h>

#define BB    8
#define N1    2048
#define N2    8192
#define C1    256
#define C2    128
#define CIN   384
#define MOUT  256
#define NTOT  (BB*N2)   // 65536 columns total

// ---------------- scratch (static __device__ arrays; no allocation) ----------
__device__ int    g_idx[BB*N2*3];
__device__ float  g_wgt[BB*N2*3];
__device__ float  g_interp[(size_t)BB*C1*N2];   // 67 MB  interpolated feat1
__device__ float  g_Y1[(size_t)BB*MOUT*N2];     // 67 MB  layer-1 raw output
__device__ float  g_scale1[MOUT], g_shift1[MOUT];
__device__ float  g_scale2[MOUT], g_shift2[MOUT];

// ---------------- 1) three_nn: top-3 nearest sparse points ------------------
__global__ void knn_kernel(const float* __restrict__ xyz2,
                           const float* __restrict__ xyz1)
{
    __shared__ float sx[N1], sy[N1], sz[N1];
    const int b = blockIdx.y;
    const float* p1 = xyz1 + (size_t)b * 3 * N1;
    for (int t = threadIdx.x; t < N1; t += blockDim.x) {
        sx[t] = p1[t];
        sy[t] = p1[N1 + t];
        sz[t] = p1[2*N1 + t];
    }
    __syncthreads();

    const int n = blockIdx.x * blockDim.x + threadIdx.x;
    const float* p2 = xyz2 + (size_t)b * 3 * N2;
    const float px = p2[n], py = p2[N2 + n], pz = p2[2*N2 + n];

    float d0 = 3.4e38f, d1 = 3.4e38f, d2v = 3.4e38f;
    int   i0 = 0, i1 = 0, i2 = 0;
    #pragma unroll 4
    for (int j = 0; j < N1; ++j) {
        float dx = px - sx[j];
        float dy = py - sy[j];
        float dz = pz - sz[j];
        float d = dx*dx + dy*dy + dz*dz;
        if (d < d2v) {
            if (d < d1) {
                d2v = d1; i2 = i1;
                if (d < d0) { d1 = d0; i1 = i0; d0 = d; i0 = j; }
                else        { d1 = d;  i1 = j; }
            } else { d2v = d; i2 = j; }
        }
    }
    d0  = fmaxf(d0,  1e-10f);
    d1  = fmaxf(d1,  1e-10f);
    d2v = fmaxf(d2v, 1e-10f);
    float r0 = 1.0f / d0, r1 = 1.0f / d1, r2 = 1.0f / d2v;
    float inv = 1.0f / (r0 + r1 + r2);
    size_t base = ((size_t)b * N2 + n) * 3;
    g_idx[base]   = i0; g_idx[base+1] = i1; g_idx[base+2] = i2;
    g_wgt[base]   = r0*inv; g_wgt[base+1] = r1*inv; g_wgt[base+2] = r2*inv;
}

// ---------------- 2) weighted gather of feat1 -> g_interp -------------------
__global__ void interp_kernel(const float* __restrict__ feat1)
{
    const int b = blockIdx.y;
    const int n = blockIdx.x * blockDim.x + threadIdx.x;
    size_t base = ((size_t)b * N2 + n) * 3;
    const int   i0 = g_idx[base], i1 = g_idx[base+1], i2 = g_idx[base+2];
    const float w0 = g_wgt[base], w1 = g_wgt[base+1], w2 = g_wgt[base+2];
    const float* f1 = feat1 + (size_t)b * C1 * N1;
    float* X = g_interp + (size_t)b * C1 * N2 + n;
    #pragma unroll 4
    for (int c = 0; c < C1; ++c) {
        const float* row = f1 + c * N1;
        X[(size_t)c * N2] = w0 * row[i0] + w1 * row[i1] + w2 * row[i2];
    }
}

// ---------------- 3/5) tiled fp32 GEMM, optional concat input / fused BN ----
// out[b, m, n2] = sum_k Wm[m,k] * A[k, (b,n2)] + bias[m]
// CONCAT: rows [0,C1) come from A1 (g_interp), rows [C1,K) from A2 (feat2)
// FUSE:   A element -> relu(a*scale[k] + shift[k])   (layer-1 BN+ReLU)
template<int K, bool CONCAT, bool FUSE>
__global__ void __launch_bounds__(256)
gemm_kernel(const float* __restrict__ Wm, const float* __restrict__ bias,
            const float* __restrict__ A1, const float* __restrict__ A2,
            const float* __restrict__ scale, const float* __restrict__ shift,
            float* __restrict__ out)
{
    constexpr int BM = 64, BN = 128, BK = 16;
    __shared__ float Ws[BK][BM];    // W transposed tile
    __shared__ float Xs[BK][BN];

    const int tid = threadIdx.x;
    const int tx  = tid & 15;       // n sub-tile (8 cols each)
    const int ty  = tid >> 4;       // m sub-tile (4 rows each)

    const int nglob = blockIdx.x * BN;
    const int b     = nglob >> 13;          // /8192
    const int n2    = nglob & (N2 - 1);
    const int m0    = blockIdx.y * BM;

    const float* A1b = A1 + (size_t)b * (CONCAT ? C1 : K) * N2 + n2;
    const float* A2b = CONCAT ? (A2 + (size_t)b * C2 * N2 + n2) : nullptr;

    float acc[4][8];
    #pragma unroll
    for (int r = 0; r < 4; ++r)
        #pragma unroll
        for (int c = 0; c < 8; ++c) acc[r][c] = 0.0f;

    const int wm = tid >> 2;            // 0..63 : m within tile
    const int wk = (tid & 3) * 4;       // 0,4,8,12 : k within tile

    for (int k0 = 0; k0 < K; k0 += BK) {
        // --- load W tile (64x16), store transposed ---
        float4 wv = *(const float4*)(Wm + (size_t)(m0 + wm) * K + k0 + wk);
        Ws[wk+0][wm] = wv.x; Ws[wk+1][wm] = wv.y;
        Ws[wk+2][wm] = wv.z; Ws[wk+3][wm] = wv.w;

        // --- load A tile (16x128) ---
        #pragma unroll
        for (int e = 0; e < 2; ++e) {
            const int ent = tid + e * 256;
            const int k   = ent >> 5;           // 0..15
            const int nq  = (ent & 31) * 4;     // col 0..124
            const int kg  = k0 + k;
            const float* src;
            if (CONCAT)
                src = (kg < C1) ? (A1b + (size_t)kg * N2)
                                : (A2b + (size_t)(kg - C1) * N2);
            else
                src = A1b + (size_t)kg * N2;
            float4 v = *(const float4*)(src + nq);
            if (FUSE) {
                const float sc = scale[kg], sh = shift[kg];
                v.x = fmaxf(fmaf(v.x, sc, sh), 0.0f);
                v.y = fmaxf(fmaf(v.y, sc, sh), 0.0f);
                v.z = fmaxf(fmaf(v.z, sc, sh), 0.0f);
                v.w = fmaxf(fmaf(v.w, sc, sh), 0.0f);
            }
            *(float4*)&Xs[k][nq] = v;
        }
        __syncthreads();

        #pragma unroll
        for (int kk = 0; kk < BK; ++kk) {
            const float4 a  = *(const float4*)&Ws[kk][ty * 4];
            const float4 x0 = *(const float4*)&Xs[kk][tx * 8];
            const float4 x1 = *(const float4*)&Xs[kk][tx * 8 + 4];
            const float av[4] = {a.x, a.y, a.z, a.w};
            const float xv[8] = {x0.x, x0.y, x0.z, x0.w, x1.x, x1.y, x1.z, x1.w};
            #pragma unroll
            for (int r = 0; r < 4; ++r)
                #pragma unroll
                for (int c = 0; c < 8; ++c)
                    acc[r][c] = fmaf(av[r], xv[c], acc[r][c]);
        }
        __syncthreads();
    }

    float* ob = out + (size_t)b * MOUT * N2 + n2;
    #pragma unroll
    for (int r = 0; r < 4; ++r) {
        const int m = m0 + ty * 4 + r;
        const float bv = bias[m];
        float4 o0 = {acc[r][0] + bv, acc[r][1] + bv, acc[r][2] + bv, acc[r][3] + bv};
        float4 o1 = {acc[r][4] + bv, acc[r][5] + bv, acc[r][6] + bv, acc[r][7] + bv};
        *(float4*)(ob + (size_t)m * N2 + tx * 8)     = o0;
        *(float4*)(ob + (size_t)m * N2 + tx * 8 + 4) = o1;
    }
}

// ---------------- 4/6) BN training-mode stats -> per-channel affine ---------
__global__ void stats_kernel(const float* __restrict__ Y,
                             const float* __restrict__ gamma,
                             const float* __restrict__ beta,
                             float* __restrict__ scale,
                             float* __restrict__ shift)
{
    const int c = blockIdx.x;
    double s = 0.0, ss = 0.0;
    for (int t = threadIdx.x; t < NTOT; t += blockDim.x) {
        const int b = t >> 13;
        const int n = t & (N2 - 1);
        const float v = Y[(size_t)b * MOUT * N2 + (size_t)c * N2 + n];
        s  += (double)v;
        ss += (double)v * (double)v;
    }
    __shared__ double rs[256], rss[256];
    rs[threadIdx.x] = s; rss[threadIdx.x] = ss;
    __syncthreads();
    for (int o = 128; o > 0; o >>= 1) {
        if (threadIdx.x < o) {
            rs[threadIdx.x]  += rs[threadIdx.x + o];
            rss[threadIdx.x] += rss[threadIdx.x + o];
        }
        __syncthreads();
    }
    if (threadIdx.x == 0) {
        const double mean = rs[0] / (double)NTOT;
        const double var  = rss[0] / (double)NTOT - mean * mean;
        const float istd  = (float)(1.0 / sqrt(var + 1e-3));
        const float sc    = gamma[c] * istd;
        scale[c] = sc;
        shift[c] = beta[c] - (float)mean * sc;
    }
}

// ---------------- 7) in-place BN+ReLU of layer-2 output ---------------------
__global__ void finalize_kernel(float* __restrict__ out)
{
    const size_t i4 = (size_t)blockIdx.x * blockDim.x + threadIdx.x; // float4 idx
    const int c = (int)((i4 >> 11) & 255);   // 8192/4 = 2048 float4 per row
    float4* p = (float4*)out + i4;
    float4 v = *p;
    const float sc = g_scale2[c], sh = g_shift2[c];
    v.x = fmaxf(fmaf(v.x, sc, sh), 0.0f);
    v.y = fmaxf(fmaf(v.y, sc, sh), 0.0f);
    v.z = fmaxf(fmaf(v.z, sc, sh), 0.0f);
    v.w = fmaxf(fmaf(v.w, sc, sh), 0.0f);
    *p = v;
}

// ---------------- launch ----------------------------------------------------
extern "C" void kernel_launch(void* const* d_in, const int* in_sizes, int n_in,
                              void* d_out, int out_size)
{
    const float* xyz2  = (const float*)d_in[0];
    const float* xyz1  = (const float*)d_in[1];
    const float* feat2 = (const float*)d_in[2];
    const float* feat1 = (const float*)d_in[3];
    const float* W1    = (const float*)d_in[4];
    const float* b1    = (const float*)d_in[5];
    const float* g1    = (const float*)d_in[6];
    const float* be1   = (const float*)d_in[7];
    const float* W2    = (const float*)d_in[8];
    const float* b2    = (const float*)d_in[9];
    const float* g2    = (const float*)d_in[10];
    const float* be2   = (const float*)d_in[11];
    float* out = (float*)d_out;

    float *p_interp, *p_Y1, *p_s1, *p_sh1, *p_s2, *p_sh2;
    cudaGetSymbolAddress((void**)&p_interp, g_interp);
    cudaGetSymbolAddress((void**)&p_Y1,     g_Y1);
    cudaGetSymbolAddress((void**)&p_s1,     g_scale1);
    cudaGetSymbolAddress((void**)&p_sh1,    g_shift1);
    cudaGetSymbolAddress((void**)&p_s2,     g_scale2);
    cudaGetSymbolAddress((void**)&p_sh2,    g_shift2);

    knn_kernel<<<dim3(N2/256, BB), 256>>>(xyz2, xyz1);
    interp_kernel<<<dim3(N2/256, BB), 256>>>(feat1);

    // layer 1: y1 = W1 @ [interp; feat2] + b1   (raw, stats afterwards)
    gemm_kernel<CIN, true, false><<<dim3(NTOT/128, MOUT/64), 256>>>(
        W1, b1, p_interp, feat2, nullptr, nullptr, p_Y1);
    stats_kernel<<<MOUT, 256>>>(p_Y1, g1, be1, p_s1, p_sh1);

    // layer 2: y2 = W2 @ relu(bn(y1)) + b2  -> d_out (raw)
    gemm_kernel<MOUT, false, true><<<dim3(NTOT/128, MOUT/64), 256>>>(
        W2, b2, p_Y1, nullptr, p_s1, p_sh1, out);
    stats_kernel<<<MOUT, 256>>>(out, g2, be2, p_s2, p_sh2);

    // in-place bn+relu on d_out
    finalize_kernel<<<(NTOT * MOUT / 4) / 256, 256>>>(out);
}

// round 3
// speedup vs baseline: 1.4533x; 1.4533x over previous
#include <cuda_runtime.h>
#include <math.h>
#include <stdint.h>

#define BB    8
#define N1    2048
#define N2    8192
#define C1    256
#define C2    128
#define CIN   384
#define MOUT  256
#define NTOT  (BB*N2)   // 65536 columns total

// ---------------- scratch (static __device__ arrays; no allocation) ----------
__device__ int    g_idx[BB*N2*3];
__device__ float  g_wgt[BB*N2*3];
__device__ float  g_interp[(size_t)BB*C1*N2];   // 67 MB  interpolated feat1
__device__ float  g_Y1[(size_t)BB*MOUT*N2];     // 67 MB  layer-1 raw output
__device__ float  g_scale1[MOUT], g_shift1[MOUT];
__device__ float  g_scale2[MOUT], g_shift2[MOUT];
// pre-transposed + tf32-split weights: [K][M] row-major
__device__ float  g_W1hi[CIN*MOUT], g_W1lo[CIN*MOUT];
__device__ float  g_W2hi[MOUT*MOUT], g_W2lo[MOUT*MOUT];
// stats partials: [channel][slice][{sum,sumsq}]
__device__ double g_part[MOUT][16][2];

__device__ __forceinline__ float tf32_trunc(float x) {
    return __int_as_float(__float_as_int(x) & 0xffffe000);
}

// ---------------- 0) prep: transpose + hi/lo split of weights ---------------
__global__ void prep_w_kernel(const float* __restrict__ W1,
                              const float* __restrict__ W2)
{
    int e = blockIdx.x * blockDim.x + threadIdx.x;
    if (e < MOUT * CIN) {
        int m = e / CIN, k = e % CIN;
        float w  = W1[e];
        float hi = tf32_trunc(w);
        g_W1hi[k * MOUT + m] = hi;
        g_W1lo[k * MOUT + m] = w - hi;
    }
    if (e < MOUT * MOUT) {
        int m = e / MOUT, k = e % MOUT;
        float w  = W2[e];
        float hi = tf32_trunc(w);
        g_W2hi[k * MOUT + m] = hi;
        g_W2lo[k * MOUT + m] = w - hi;
    }
}

// ---------------- 1) three_nn: top-3 nearest sparse points ------------------
__global__ void knn_kernel(const float* __restrict__ xyz2,
                           const float* __restrict__ xyz1)
{
    __shared__ float sx[N1], sy[N1], sz[N1];
    const int b = blockIdx.y;
    const float* p1 = xyz1 + (size_t)b * 3 * N1;
    for (int t = threadIdx.x; t < N1; t += blockDim.x) {
        sx[t] = p1[t];
        sy[t] = p1[N1 + t];
        sz[t] = p1[2*N1 + t];
    }
    __syncthreads();

    const int n = blockIdx.x * blockDim.x + threadIdx.x;
    const float* p2 = xyz2 + (size_t)b * 3 * N2;
    const float px = p2[n], py = p2[N2 + n], pz = p2[2*N2 + n];

    float d0 = 3.4e38f, d1 = 3.4e38f, d2v = 3.4e38f;
    int   i0 = 0, i1 = 0, i2 = 0;
    #pragma unroll 4
    for (int j = 0; j < N1; ++j) {
        float dx = px - sx[j];
        float dy = py - sy[j];
        float dz = pz - sz[j];
        float d = dx*dx + dy*dy + dz*dz;
        if (d < d2v) {
            if (d < d1) {
                d2v = d1; i2 = i1;
                if (d < d0) { d1 = d0; i1 = i0; d0 = d; i0 = j; }
                else        { d1 = d;  i1 = j; }
            } else { d2v = d; i2 = j; }
        }
    }
    d0  = fmaxf(d0,  1e-10f);
    d1  = fmaxf(d1,  1e-10f);
    d2v = fmaxf(d2v, 1e-10f);
    float r0 = 1.0f / d0, r1 = 1.0f / d1, r2 = 1.0f / d2v;
    float inv = 1.0f / (r0 + r1 + r2);
    size_t base = ((size_t)b * N2 + n) * 3;
    g_idx[base]   = i0; g_idx[base+1] = i1; g_idx[base+2] = i2;
    g_wgt[base]   = r0*inv; g_wgt[base+1] = r1*inv; g_wgt[base+2] = r2*inv;
}

// ---------------- 2) weighted gather of feat1 -> g_interp -------------------
__global__ void interp_kernel(const float* __restrict__ feat1)
{
    const int b = blockIdx.y;
    const int n = blockIdx.x * blockDim.x + threadIdx.x;
    size_t base = ((size_t)b * N2 + n) * 3;
    const int   i0 = g_idx[base], i1 = g_idx[base+1], i2 = g_idx[base+2];
    const float w0 = g_wgt[base], w1 = g_wgt[base+1], w2 = g_wgt[base+2];
    const float* f1 = feat1 + (size_t)b * C1 * N1;
    float* X = g_interp + (size_t)b * C1 * N2 + n;
    #pragma unroll 4
    for (int c = 0; c < C1; ++c) {
        const float* row = f1 + c * N1;
        X[(size_t)c * N2] = w0 * row[i0] + w1 * row[i1] + w2 * row[i2];
    }
}

// ---------------- mma.sync m16n8k8 tf32 wrapper -----------------------------
__device__ __forceinline__ void mma_tf32(float* d, const uint32_t* a, const uint32_t* b)
{
    asm volatile(
        "mma.sync.aligned.m16n8k8.row.col.f32.tf32.tf32.f32 "
        "{%0,%1,%2,%3}, {%4,%5,%6,%7}, {%8,%9}, {%0,%1,%2,%3};\n"
        : "+f"(d[0]), "+f"(d[1]), "+f"(d[2]), "+f"(d[3])
        : "r"(a[0]), "r"(a[1]), "r"(a[2]), "r"(a[3]),
          "r"(b[0]), "r"(b[1]));
}

// ---------------- 3/5) tensor-core GEMM (3xTF32), BM=256 BN=64 BK=16 --------
// out[b, m, n2] = sum_k W[m,k] * X[k, (b,n2)] + bias[m]
// W pre-transposed+split into Whi/Wlo [K][256].
// CONCAT: X rows [0,C1) from A1 (g_interp), [C1,K) from A2 (feat2)
// FUSE:   X element -> relu(x*scale[k] + shift[k])
template<int K, bool CONCAT, bool FUSE>
__global__ void __launch_bounds__(512)
gemm_tc_kernel(const float* __restrict__ Whi, const float* __restrict__ Wlo,
               const float* __restrict__ bias,
               const float* __restrict__ A1, const float* __restrict__ A2,
               const float* __restrict__ scale, const float* __restrict__ shift,
               float* __restrict__ out)
{
    constexpr int BN = 64, BK = 16;
    constexpr int MP = 264;   // padded M row for conflict-free a-frag LDS
    constexpr int KP = 20;    // padded K row for conflict-free b-frag LDS
    __shared__ float Wsh[BK][MP];
    __shared__ float Wsl[BK][MP];
    __shared__ float Xs[BN][KP];

    const int tid  = threadIdx.x;
    const int lane = tid & 31;
    const int wid  = tid >> 5;          // 0..15
    const int g    = lane >> 2;         // groupID
    const int tig  = lane & 3;          // thread in group
    const int m0w  = (wid & 3) * 64;    // warp m base
    const int n0w  = (wid >> 2) * 16;   // warp n base

    const int nglob = blockIdx.x * BN;
    const int b     = nglob >> 13;          // /8192
    const int n2    = nglob & (N2 - 1);

    const float* A1b = A1 + (size_t)b * (CONCAT ? C1 : K) * N2 + n2;
    const float* A2b = CONCAT ? (A2 + (size_t)b * C2 * N2 + n2) : nullptr;

    float acc[4][2][4];                 // [mt][nt][frag]
    #pragma unroll
    for (int mt = 0; mt < 4; ++mt)
        #pragma unroll
        for (int nt = 0; nt < 2; ++nt)
            #pragma unroll
            for (int r = 0; r < 4; ++r) acc[mt][nt][r] = 0.0f;

    for (int k0 = 0; k0 < K; k0 += BK) {
        // --- W tiles: [16][256] hi+lo, coalesced float4, 2 tasks/thread ---
        #pragma unroll
        for (int q = 0; q < 2; ++q) {
            const int task = tid + q * 512;          // 0..1023
            const int kr   = task >> 6;              // 0..15
            const int m4   = (task & 63) * 4;        // 0..252
            const size_t go = (size_t)(k0 + kr) * MOUT + m4;
            *(float4*)&Wsh[kr][m4] = *(const float4*)(Whi + go);
            *(float4*)&Wsl[kr][m4] = *(const float4*)(Wlo + go);
        }
        // --- X tile: 16 rows x 64 cols, stored transposed Xs[n][k] ---
        if (tid < 256) {
            const int kr = tid >> 4;                 // 0..15
            const int n4 = (tid & 15) * 4;           // 0..60
            const int kg = k0 + kr;
            const float* src;
            if (CONCAT)
                src = (kg < C1) ? (A1b + (size_t)kg * N2)
                                : (A2b + (size_t)(kg - C1) * N2);
            else
                src = A1b + (size_t)kg * N2;
            float4 v = *(const float4*)(src + n4);
            if (FUSE) {
                const float sc = scale[kg], sh = shift[kg];
                v.x = fmaxf(fmaf(v.x, sc, sh), 0.0f);
                v.y = fmaxf(fmaf(v.y, sc, sh), 0.0f);
                v.z = fmaxf(fmaf(v.z, sc, sh), 0.0f);
                v.w = fmaxf(fmaf(v.w, sc, sh), 0.0f);
            }
            Xs[n4+0][kr] = v.x;
            Xs[n4+1][kr] = v.y;
            Xs[n4+2][kr] = v.z;
            Xs[n4+3][kr] = v.w;
        }
        __syncthreads();

        #pragma unroll
        for (int ks = 0; ks < BK; ks += 8) {
            // b-fragments (raw = hi operand, HW truncates; lo = residual)
            uint32_t bh[2][2], bl[2][2];
            #pragma unroll
            for (int nt = 0; nt < 2; ++nt) {
                const int nb = n0w + nt * 8 + g;
                const float b0 = Xs[nb][ks + tig];
                const float b1 = Xs[nb][ks + tig + 4];
                bh[nt][0] = __float_as_uint(b0);
                bh[nt][1] = __float_as_uint(b1);
                bl[nt][0] = __float_as_uint(b0 - tf32_trunc(b0));
                bl[nt][1] = __float_as_uint(b1 - tf32_trunc(b1));
            }
            #pragma unroll
            for (int mt = 0; mt < 4; ++mt) {
                const int mb = m0w + mt * 16 + g;
                uint32_t ah[4], al[4];
                ah[0] = __float_as_uint(Wsh[ks + tig    ][mb]);
                ah[1] = __float_as_uint(Wsh[ks + tig    ][mb + 8]);
                ah[2] = __float_as_uint(Wsh[ks + tig + 4][mb]);
                ah[3] = __float_as_uint(Wsh[ks + tig + 4][mb + 8]);
                al[0] = __float_as_uint(Wsl[ks + tig    ][mb]);
                al[1] = __float_as_uint(Wsl[ks + tig    ][mb + 8]);
                al[2] = __float_as_uint(Wsl[ks + tig + 4][mb]);
                al[3] = __float_as_uint(Wsl[ks + tig + 4][mb + 8]);
                #pragma unroll
                for (int nt = 0; nt < 2; ++nt) {
                    mma_tf32(acc[mt][nt], ah, bh[nt]);   // hi*hi
                    mma_tf32(acc[mt][nt], ah, bl[nt]);   // hi*lo
                    mma_tf32(acc[mt][nt], al, bh[nt]);   // lo*hi
                }
            }
        }
        __syncthreads();
    }

    // epilogue: c0:(g, 2t) c1:(g, 2t+1) c2:(g+8, 2t) c3:(g+8, 2t+1)
    float* ob = out + (size_t)b * MOUT * N2 + n2;
    #pragma unroll
    for (int mt = 0; mt < 4; ++mt) {
        const int m = m0w + mt * 16 + g;
        const float bv0 = bias[m];
        const float bv8 = bias[m + 8];
        #pragma unroll
        for (int nt = 0; nt < 2; ++nt) {
            const int n = n0w + nt * 8 + 2 * tig;
            float2 lo = { acc[mt][nt][0] + bv0, acc[mt][nt][1] + bv0 };
            float2 hi = { acc[mt][nt][2] + bv8, acc[mt][nt][3] + bv8 };
            *(float2*)(ob + (size_t)m       * N2 + n) = lo;
            *(float2*)(ob + (size_t)(m + 8) * N2 + n) = hi;
        }
    }
}

// ---------------- 4/6) BN stats, two-stage deterministic --------------------
__global__ void stats1_kernel(const float* __restrict__ Y)
{
    const int c     = blockIdx.y;
    const int slice = blockIdx.x;          // 0..15
    // slice covers 4096 contiguous n within one (b, half): t = slice*4096 + i
    const int b  = (slice * 4096) >> 13;
    const int n0 = (slice * 4096) & (N2 - 1);
    const float* src = Y + (size_t)b * MOUT * N2 + (size_t)c * N2 + n0;

    double s = 0.0, ss = 0.0;
    for (int i = threadIdx.x; i < 1024; i += 256) {       // 1024 float4
        float4 v = *(const float4*)(src + i * 4);
        s  += (double)v.x + (double)v.y + (double)v.z + (double)v.w;
        ss += (double)v.x*v.x + (double)v.y*v.y + (double)v.z*v.z + (double)v.w*v.w;
    }
    __shared__ double rs[256], rss[256];
    rs[threadIdx.x] = s; rss[threadIdx.x] = ss;
    __syncthreads();
    for (int o = 128; o > 0; o >>= 1) {
        if (threadIdx.x < o) {
            rs[threadIdx.x]  += rs[threadIdx.x + o];
            rss[threadIdx.x] += rss[threadIdx.x + o];
        }
        __syncthreads();
    }
    if (threadIdx.x == 0) {
        g_part[c][slice][0] = rs[0];
        g_part[c][slice][1] = rss[0];
    }
}

__global__ void stats2_kernel(const float* __restrict__ gamma,
                              const float* __restrict__ beta,
                              float* __restrict__ scale,
                              float* __restrict__ shift)
{
    const int c = threadIdx.x;             // 256 threads, 1 block
    double s = 0.0, ss = 0.0;
    #pragma unroll
    for (int j = 0; j < 16; ++j) { s += g_part[c][j][0]; ss += g_part[c][j][1]; }
    const double mean = s / (double)NTOT;
    const double var  = ss / (double)NTOT - mean * mean;
    const float istd  = (float)(1.0 / sqrt(var + 1e-3));
    const float sc    = gamma[c] * istd;
    scale[c] = sc;
    shift[c] = beta[c] - (float)mean * sc;
}

// ---------------- 7) in-place BN+ReLU of layer-2 output ---------------------
__global__ void finalize_kernel(float* __restrict__ out)
{
    const size_t i4 = (size_t)blockIdx.x * blockDim.x + threadIdx.x;
    const int c = (int)((i4 >> 11) & 255);   // 8192/4 = 2048 float4 per row
    float4* p = (float4*)out + i4;
    float4 v = *p;
    const float sc = g_scale2[c], sh = g_shift2[c];
    v.x = fmaxf(fmaf(v.x, sc, sh), 0.0f);
    v.y = fmaxf(fmaf(v.y, sc, sh), 0.0f);
    v.z = fmaxf(fmaf(v.z, sc, sh), 0.0f);
    v.w = fmaxf(fmaf(v.w, sc, sh), 0.0f);
    *p = v;
}

// ---------------- launch ----------------------------------------------------
extern "C" void kernel_launch(void* const* d_in, const int* in_sizes, int n_in,
                              void* d_out, int out_size)
{
    const float* xyz2  = (const float*)d_in[0];
    const float* xyz1  = (const float*)d_in[1];
    const float* feat2 = (const float*)d_in[2];
    const float* feat1 = (const float*)d_in[3];
    const float* W1    = (const float*)d_in[4];
    const float* b1    = (const float*)d_in[5];
    const float* g1    = (const float*)d_in[6];
    const float* be1   = (const float*)d_in[7];
    const float* W2    = (const float*)d_in[8];
    const float* b2    = (const float*)d_in[9];
    const float* g2    = (const float*)d_in[10];
    const float* be2   = (const float*)d_in[11];
    float* out = (float*)d_out;

    float *p_interp, *p_Y1, *p_s1, *p_sh1, *p_s2, *p_sh2;
    float *p_W1hi, *p_W1lo, *p_W2hi, *p_W2lo;
    cudaGetSymbolAddress((void**)&p_interp, g_interp);
    cudaGetSymbolAddress((void**)&p_Y1,     g_Y1);
    cudaGetSymbolAddress((void**)&p_s1,     g_scale1);
    cudaGetSymbolAddress((void**)&p_sh1,    g_shift1);
    cudaGetSymbolAddress((void**)&p_s2,     g_scale2);
    cudaGetSymbolAddress((void**)&p_sh2,    g_shift2);
    cudaGetSymbolAddress((void**)&p_W1hi,   g_W1hi);
    cudaGetSymbolAddress((void**)&p_W1lo,   g_W1lo);
    cudaGetSymbolAddress((void**)&p_W2hi,   g_W2hi);
    cudaGetSymbolAddress((void**)&p_W2lo,   g_W2lo);

    prep_w_kernel<<<(MOUT*CIN + 255)/256, 256>>>(W1, W2);
    knn_kernel<<<dim3(N2/256, BB), 256>>>(xyz2, xyz1);
    interp_kernel<<<dim3(N2/256, BB), 256>>>(feat1);

    // layer 1: y1 = W1 @ [interp; feat2] + b1   (raw, stats afterwards)
    gemm_tc_kernel<CIN, true, false><<<NTOT/64, 512>>>(
        p_W1hi, p_W1lo, b1, p_interp, feat2, nullptr, nullptr, p_Y1);
    stats1_kernel<<<dim3(16, MOUT), 256>>>(p_Y1);
    stats2_kernel<<<1, MOUT>>>(g1, be1, p_s1, p_sh1);

    // layer 2: y2 = W2 @ relu(bn(y1)) + b2  -> d_out (raw)
    gemm_tc_kernel<MOUT, false, true><<<NTOT/64, 512>>>(
        p_W2hi, p_W2lo, b2, p_Y1, nullptr, p_s1, p_sh1, out);
    stats1_kernel<<<dim3(16, MOUT), 256>>>(out);
    stats2_kernel<<<1, MOUT>>>(g2, be2, p_s2, p_sh2);

    // in-place bn+relu on d_out
    finalize_kernel<<<(NTOT * MOUT / 4) / 256, 256>>>(out);
}

// round 4
// speedup vs baseline: 1.5307x; 1.0532x over previous
#include <cuda_runtime.h>
#include <math.h>
#include <stdint.h>

#define BB    8
#define N1    2048
#define N2    8192
#define C1    256
#define C2    128
#define CIN   384
#define MOUT  256
#define NTOT  (BB*N2)     // 65536 columns
#define NBLK  (NTOT/64)   // 1024 GEMM blocks

// ---------------- scratch (static __device__; no allocation) ----------------
__device__ int    g_idx[BB*N2*3];
__device__ float  g_wgt[BB*N2*3];
__device__ float  g_interp[(size_t)BB*C1*N2];   // 67 MB
__device__ float  g_Y1[(size_t)BB*MOUT*N2];     // 67 MB
__device__ float  g_scale1[MOUT], g_shift1[MOUT];
__device__ float  g_scale2[MOUT], g_shift2[MOUT];
__device__ float2 g_bpart[(size_t)NBLK*MOUT];   // per-block {sum,sumsq}

__device__ __forceinline__ float tf32_trunc(float x) {
    return __int_as_float(__float_as_int(x) & 0xffffe000);
}

// ---------------- 1) three_nn ------------------------------------------------
__global__ void knn_kernel(const float* __restrict__ xyz2,
                           const float* __restrict__ xyz1)
{
    __shared__ float sx[N1], sy[N1], sz[N1];
    const int b = blockIdx.y;
    const float* p1 = xyz1 + (size_t)b * 3 * N1;
    for (int t = threadIdx.x; t < N1; t += blockDim.x) {
        sx[t] = p1[t];
        sy[t] = p1[N1 + t];
        sz[t] = p1[2*N1 + t];
    }
    __syncthreads();

    const int n = blockIdx.x * blockDim.x + threadIdx.x;
    const float* p2 = xyz2 + (size_t)b * 3 * N2;
    const float px = p2[n], py = p2[N2 + n], pz = p2[2*N2 + n];

    float d0 = 3.4e38f, d1 = 3.4e38f, d2v = 3.4e38f;
    int   i0 = 0, i1 = 0, i2 = 0;
    #pragma unroll 4
    for (int j = 0; j < N1; ++j) {
        float dx = px - sx[j];
        float dy = py - sy[j];
        float dz = pz - sz[j];
        float d = dx*dx + dy*dy + dz*dz;
        if (d < d2v) {
            if (d < d1) {
                d2v = d1; i2 = i1;
                if (d < d0) { d1 = d0; i1 = i0; d0 = d; i0 = j; }
                else        { d1 = d;  i1 = j; }
            } else { d2v = d; i2 = j; }
        }
    }
    d0  = fmaxf(d0,  1e-10f);
    d1  = fmaxf(d1,  1e-10f);
    d2v = fmaxf(d2v, 1e-10f);
    float r0 = 1.0f / d0, r1 = 1.0f / d1, r2 = 1.0f / d2v;
    float inv = 1.0f / (r0 + r1 + r2);
    size_t base = ((size_t)b * N2 + n) * 3;
    g_idx[base]   = i0; g_idx[base+1] = i1; g_idx[base+2] = i2;
    g_wgt[base]   = r0*inv; g_wgt[base+1] = r1*inv; g_wgt[base+2] = r2*inv;
}

// ---------------- 2) weighted gather -> g_interp ----------------------------
__global__ void interp_kernel(const float* __restrict__ feat1)
{
    const int b = blockIdx.y;
    const int n = blockIdx.x * blockDim.x + threadIdx.x;
    size_t base = ((size_t)b * N2 + n) * 3;
    const int   i0 = g_idx[base], i1 = g_idx[base+1], i2 = g_idx[base+2];
    const float w0 = g_wgt[base], w1 = g_wgt[base+1], w2 = g_wgt[base+2];
    const float* f1 = feat1 + (size_t)b * C1 * N1;
    float* X = g_interp + (size_t)b * C1 * N2 + n;
    #pragma unroll 4
    for (int c = 0; c < C1; ++c) {
        const float* row = f1 + c * N1;
        X[(size_t)c * N2] = w0 * row[i0] + w1 * row[i1] + w2 * row[i2];
    }
}

// ---------------- mma / ldmatrix wrappers -----------------------------------
__device__ __forceinline__ void mma_tf32(float* d, const uint32_t* a, const uint32_t* b)
{
    asm volatile(
        "mma.sync.aligned.m16n8k8.row.col.f32.tf32.tf32.f32 "
        "{%0,%1,%2,%3}, {%4,%5,%6,%7}, {%8,%9}, {%0,%1,%2,%3};\n"
        : "+f"(d[0]), "+f"(d[1]), "+f"(d[2]), "+f"(d[3])
        : "r"(a[0]), "r"(a[1]), "r"(a[2]), "r"(a[3]),
          "r"(b[0]), "r"(b[1]));
}

__device__ __forceinline__ void ldsm_x4(uint32_t* r, uint32_t saddr)
{
    asm volatile(
        "ldmatrix.sync.aligned.m8n8.x4.shared.b16 {%0,%1,%2,%3}, [%4];\n"
        : "=r"(r[0]), "=r"(r[1]), "=r"(r[2]), "=r"(r[3])
        : "r"(saddr));
}

// ---------------- 3/5) tensor-core GEMM, 3xTF32, fused stats ----------------
// out[b,m,n2] = sum_k W[m,k]*X[k,(b,n2)] + bias[m]; W in original [M][K] layout.
// CONCAT: X rows [0,C1) from A1 (g_interp), rest from A2 (feat2).
// FUSE:   X -> relu(x*scale[k] + shift[k]).
// Also emits per-block per-channel {sum, sumsq} into bpart (fused BN stats).
template<int K, bool CONCAT, bool FUSE>
__global__ void __launch_bounds__(512, 2)
gemm_tc_kernel(const float* __restrict__ W, const float* __restrict__ bias,
               const float* __restrict__ A1, const float* __restrict__ A2,
               const float* __restrict__ scale, const float* __restrict__ shift,
               float* __restrict__ out, float2* __restrict__ bpart)
{
    constexpr int SKW = 20;   // W row pad (words): conflict-free ldmatrix
    constexpr int SN  = 72;   // X row pad (words): conflict-free LDS + STS.128
    __shared__ float Wsh[256][SKW];    // 20 KB
    __shared__ float Xs[16][SN];       // 4.6 KB

    const int tid   = threadIdx.x;
    const int lane  = tid & 31;
    const int wid   = tid >> 5;         // 0..15
    const int g     = lane >> 2;
    const int tig   = lane & 3;
    const int mwarp = wid >> 1;         // 0..7 -> m base mwarp*32
    const int nwarp = wid & 1;          // 0..1 -> n base nwarp*32

    const int nglob = blockIdx.x * 64;
    const int b     = nglob >> 13;
    const int n2    = nglob & (N2 - 1);

    const float* A1b = A1 + (size_t)b * (CONCAT ? C1 : K) * N2 + n2;
    const float* A2b = CONCAT ? (A2 + (size_t)b * C2 * N2 + n2) : nullptr;

    float acc[2][4][4];
    #pragma unroll
    for (int mt = 0; mt < 2; ++mt)
        #pragma unroll
        for (int nt = 0; nt < 4; ++nt)
            #pragma unroll
            for (int r = 0; r < 4; ++r) acc[mt][nt][r] = 0.0f;

    // ldmatrix lane address (A fragments): x4 matrices cover m16 x k8
    const uint32_t wbase = (uint32_t)__cvta_generic_to_shared(&Wsh[0][0]);
    const int rowoff  = ((lane >> 3) & 1) * 8 + (lane & 7);
    const int wordoff = (lane >> 4) * 4;      // 0 or 4
    const uint32_t aAddr0 = wbase + ((((mwarp*32 + rowoff) * SKW) + wordoff) << 2);

    const int xkr = tid >> 4;            // X loader: k row (tid<256)
    const int xn4 = (tid & 15) * 4;      //           n quad

    for (int k0 = 0; k0 < K; k0 += 16) {
        // W tile: 256 m x 16 k, float4, 2 tasks/thread
        #pragma unroll
        for (int q = 0; q < 2; ++q) {
            const int t  = tid + q * 512;
            const int m  = t >> 2;
            const int kc = (t & 3) * 4;
            *(float4*)&Wsh[m][kc] = *(const float4*)(W + (size_t)m * K + k0 + kc);
        }
        // X tile: 16 k x 64 n
        if (tid < 256) {
            const int kg = k0 + xkr;
            const float* src;
            if (CONCAT)
                src = (kg < C1) ? (A1b + (size_t)kg * N2)
                                : (A2b + (size_t)(kg - C1) * N2);
            else
                src = A1b + (size_t)kg * N2;
            float4 v = *(const float4*)(src + xn4);
            if (FUSE) {
                const float sc = scale[kg], sh = shift[kg];
                v.x = fmaxf(fmaf(v.x, sc, sh), 0.0f);
                v.y = fmaxf(fmaf(v.y, sc, sh), 0.0f);
                v.z = fmaxf(fmaf(v.z, sc, sh), 0.0f);
                v.w = fmaxf(fmaf(v.w, sc, sh), 0.0f);
            }
            *(float4*)&Xs[xkr][xn4] = v;
        }
        __syncthreads();

        #pragma unroll
        for (int ks = 0; ks < 16; ks += 8) {
            #pragma unroll
            for (int mt = 0; mt < 2; ++mt) {
                uint32_t ah[4], al[4];
                ldsm_x4(ah, aAddr0 + ((mt * 16 * SKW + ks) << 2));
                #pragma unroll
                for (int i = 0; i < 4; ++i) {
                    const float a = __uint_as_float(ah[i]);
                    al[i] = __float_as_uint(a - tf32_trunc(a));
                }
                #pragma unroll
                for (int nt = 0; nt < 4; ++nt) {
                    const int nn = nwarp * 32 + nt * 8 + g;
                    const float b0 = Xs[ks + tig][nn];
                    const float b1 = Xs[ks + tig + 4][nn];
                    uint32_t bh[2] = { __float_as_uint(b0), __float_as_uint(b1) };
                    uint32_t bl[2] = { __float_as_uint(b0 - tf32_trunc(b0)),
                                       __float_as_uint(b1 - tf32_trunc(b1)) };
                    mma_tf32(acc[mt][nt], ah, bh);   // hi*hi
                    mma_tf32(acc[mt][nt], ah, bl);   // hi*lo
                    mma_tf32(acc[mt][nt], al, bh);   // lo*hi
                }
            }
        }
        __syncthreads();
    }

    // ---- epilogue: bias add, store, fused per-channel stats ----
    float* part = &Wsh[0][0];   // reuse: [nwarp][256][{s,ss}] = 1024 floats
    float* ob = out + (size_t)b * MOUT * N2 + n2;
    #pragma unroll
    for (int mt = 0; mt < 2; ++mt) {
        #pragma unroll
        for (int h = 0; h < 2; ++h) {
            const int m  = mwarp * 32 + mt * 16 + h * 8 + g;
            const float bv = bias[m];
            float s = 0.0f, ss = 0.0f;
            #pragma unroll
            for (int nt = 0; nt < 4; ++nt) {
                const float v0 = acc[mt][nt][h*2+0] + bv;
                const float v1 = acc[mt][nt][h*2+1] + bv;
                const int n = nwarp * 32 + nt * 8 + 2 * tig;
                *(float2*)(ob + (size_t)m * N2 + n) = make_float2(v0, v1);
                s  += v0 + v1;
                ss += v0*v0 + v1*v1;
            }
            s  += __shfl_xor_sync(0xffffffffu, s, 1);
            s  += __shfl_xor_sync(0xffffffffu, s, 2);
            ss += __shfl_xor_sync(0xffffffffu, ss, 1);
            ss += __shfl_xor_sync(0xffffffffu, ss, 2);
            if (tig == 0) {
                part[(nwarp * 256 + m) * 2 + 0] = s;
                part[(nwarp * 256 + m) * 2 + 1] = ss;
            }
        }
    }
    __syncthreads();
    if (tid < 256) {
        float2 r;
        r.x = part[tid * 2]     + part[(256 + tid) * 2];
        r.y = part[tid * 2 + 1] + part[(256 + tid) * 2 + 1];
        bpart[(size_t)blockIdx.x * MOUT + tid] = r;
    }
}

// ---------------- 4/6) stage-2 stats reduce ---------------------------------
__global__ void stats2_kernel(const float* __restrict__ gamma,
                              const float* __restrict__ beta,
                              float* __restrict__ scale,
                              float* __restrict__ shift)
{
    const int c = blockIdx.x;
    double s = 0.0, ss = 0.0;
    for (int j = threadIdx.x; j < NBLK; j += 256) {
        const float2 p = g_bpart[(size_t)j * MOUT + c];
        s  += (double)p.x;
        ss += (double)p.y;
    }
    __shared__ double rs[256], rss[256];
    rs[threadIdx.x] = s; rss[threadIdx.x] = ss;
    __syncthreads();
    for (int o = 128; o > 0; o >>= 1) {
        if (threadIdx.x < o) {
            rs[threadIdx.x]  += rs[threadIdx.x + o];
            rss[threadIdx.x] += rss[threadIdx.x + o];
        }
        __syncthreads();
    }
    if (threadIdx.x == 0) {
        const double mean = rs[0] / (double)NTOT;
        const double var  = rss[0] / (double)NTOT - mean * mean;
        const float istd  = (float)(1.0 / sqrt(var + 1e-3));
        const float sc    = gamma[c] * istd;
        scale[c] = sc;
        shift[c] = beta[c] - (float)mean * sc;
    }
}

// ---------------- 7) in-place BN+ReLU of layer-2 output ---------------------
__global__ void finalize_kernel(float* __restrict__ out)
{
    const size_t i4 = (size_t)blockIdx.x * blockDim.x + threadIdx.x;
    const int c = (int)((i4 >> 11) & 255);
    float4* p = (float4*)out + i4;
    float4 v = *p;
    const float sc = g_scale2[c], sh = g_shift2[c];
    v.x = fmaxf(fmaf(v.x, sc, sh), 0.0f);
    v.y = fmaxf(fmaf(v.y, sc, sh), 0.0f);
    v.z = fmaxf(fmaf(v.z, sc, sh), 0.0f);
    v.w = fmaxf(fmaf(v.w, sc, sh), 0.0f);
    *p = v;
}

// ---------------- launch ----------------------------------------------------
extern "C" void kernel_launch(void* const* d_in, const int* in_sizes, int n_in,
                              void* d_out, int out_size)
{
    const float* xyz2  = (const float*)d_in[0];
    const float* xyz1  = (const float*)d_in[1];
    const float* feat2 = (const float*)d_in[2];
    const float* feat1 = (const float*)d_in[3];
    const float* W1    = (const float*)d_in[4];
    const float* b1    = (const float*)d_in[5];
    const float* g1    = (const float*)d_in[6];
    const float* be1   = (const float*)d_in[7];
    const float* W2    = (const float*)d_in[8];
    const float* b2    = (const float*)d_in[9];
    const float* g2    = (const float*)d_in[10];
    const float* be2   = (const float*)d_in[11];
    float* out = (float*)d_out;

    float  *p_interp, *p_Y1, *p_s1, *p_sh1, *p_s2, *p_sh2;
    float2 *p_bpart;
    cudaGetSymbolAddress((void**)&p_interp, g_interp);
    cudaGetSymbolAddress((void**)&p_Y1,     g_Y1);
    cudaGetSymbolAddress((void**)&p_s1,     g_scale1);
    cudaGetSymbolAddress((void**)&p_sh1,    g_shift1);
    cudaGetSymbolAddress((void**)&p_s2,     g_scale2);
    cudaGetSymbolAddress((void**)&p_sh2,    g_shift2);
    cudaGetSymbolAddress((void**)&p_bpart,  g_bpart);

    knn_kernel<<<dim3(N2/256, BB), 256>>>(xyz2, xyz1);
    interp_kernel<<<dim3(N2/256, BB), 256>>>(feat1);

    // layer 1: y1 = W1 @ [interp; feat2] + b1 (raw) + fused stats partials
    gemm_tc_kernel<CIN, true, false><<<NBLK, 512>>>(
        W1, b1, p_interp, feat2, nullptr, nullptr, p_Y1, p_bpart);
    stats2_kernel<<<MOUT, 256>>>(g1, be1, p_s1, p_sh1);

    // layer 2: y2 = W2 @ relu(bn(y1)) + b2 -> d_out (raw) + fused stats
    gemm_tc_kernel<MOUT, false, true><<<NBLK, 512>>>(
        W2, b2, p_Y1, nullptr, p_s1, p_sh1, out, p_bpart);
    stats2_kernel<<<MOUT, 256>>>(g2, be2, p_s2, p_sh2);

    finalize_kernel<<<(NTOT * MOUT / 4) / 256, 256>>>(out);
}

// round 5
// speedup vs baseline: 1.8693x; 1.2212x over previous
#include <cuda_runtime.h>
#include <math.h>
#include <stdint.h>

#define BB    8
#define N1    2048
#define N2    8192
#define C1    256
#define C2    128
#define CIN   384
#define MOUT  256
#define NTOT  (BB*N2)     // 65536 columns
#define NBLK  (NTOT/64)   // 1024 GEMM blocks

// pipeline geometry
#define PSTAGES   3
#define W_STAGE   (256*20*4)         // 20480 B per W stage
#define X_STAGE   (16*72*4)          // 4608 B per X stage
#define WOFF      0
#define XOFF      (PSTAGES*W_STAGE)                 // 61440
#define SCOFF     (XOFF + PSTAGES*X_STAGE)          // 75264
#define SMEM_DYN  (SCOFF + 2*256*4)                 // 77312

// ---------------- scratch (static __device__; no allocation) ----------------
__device__ int    g_idx[BB*N2*3];
__device__ float  g_wgt[BB*N2*3];
__device__ float  g_interp[(size_t)BB*C1*N2];   // 67 MB
__device__ float  g_Y1[(size_t)BB*MOUT*N2];     // 67 MB
__device__ float  g_scale1[MOUT], g_shift1[MOUT];
__device__ float  g_scale2[MOUT], g_shift2[MOUT];
__device__ float2 g_bpart[(size_t)NBLK*MOUT];   // per-block {sum,sumsq}

__device__ __forceinline__ float tf32_trunc(float x) {
    return __int_as_float(__float_as_int(x) & 0xffffe000);
}

// ---------------- 1) three_nn ------------------------------------------------
__global__ void knn_kernel(const float* __restrict__ xyz2,
                           const float* __restrict__ xyz1)
{
    __shared__ float sx[N1], sy[N1], sz[N1];
    const int b = blockIdx.y;
    const float* p1 = xyz1 + (size_t)b * 3 * N1;
    for (int t = threadIdx.x; t < N1; t += blockDim.x) {
        sx[t] = p1[t];
        sy[t] = p1[N1 + t];
        sz[t] = p1[2*N1 + t];
    }
    __syncthreads();

    const int n = blockIdx.x * blockDim.x + threadIdx.x;
    const float* p2 = xyz2 + (size_t)b * 3 * N2;
    const float px = p2[n], py = p2[N2 + n], pz = p2[2*N2 + n];

    float d0 = 3.4e38f, d1 = 3.4e38f, d2v = 3.4e38f;
    int   i0 = 0, i1 = 0, i2 = 0;
    #pragma unroll 4
    for (int j = 0; j < N1; ++j) {
        float dx = px - sx[j];
        float dy = py - sy[j];
        float dz = pz - sz[j];
        float d = dx*dx + dy*dy + dz*dz;
        if (d < d2v) {
            if (d < d1) {
                d2v = d1; i2 = i1;
                if (d < d0) { d1 = d0; i1 = i0; d0 = d; i0 = j; }
                else        { d1 = d;  i1 = j; }
            } else { d2v = d; i2 = j; }
        }
    }
    d0  = fmaxf(d0,  1e-10f);
    d1  = fmaxf(d1,  1e-10f);
    d2v = fmaxf(d2v, 1e-10f);
    float r0 = 1.0f / d0, r1 = 1.0f / d1, r2 = 1.0f / d2v;
    float inv = 1.0f / (r0 + r1 + r2);
    size_t base = ((size_t)b * N2 + n) * 3;
    g_idx[base]   = i0; g_idx[base+1] = i1; g_idx[base+2] = i2;
    g_wgt[base]   = r0*inv; g_wgt[base+1] = r1*inv; g_wgt[base+2] = r2*inv;
}

// ---------------- 2) weighted gather -> g_interp ----------------------------
__global__ void interp_kernel(const float* __restrict__ feat1)
{
    const int b = blockIdx.y;
    const int n = blockIdx.x * blockDim.x + threadIdx.x;
    size_t base = ((size_t)b * N2 + n) * 3;
    const int   i0 = g_idx[base], i1 = g_idx[base+1], i2 = g_idx[base+2];
    const float w0 = g_wgt[base], w1 = g_wgt[base+1], w2 = g_wgt[base+2];
    const float* f1 = feat1 + (size_t)b * C1 * N1;
    float* X = g_interp + (size_t)b * C1 * N2 + n;
    #pragma unroll 4
    for (int c = 0; c < C1; ++c) {
        const float* row = f1 + c * N1;
        X[(size_t)c * N2] = w0 * row[i0] + w1 * row[i1] + w2 * row[i2];
    }
}

// ---------------- mma / ldmatrix / cp.async wrappers ------------------------
__device__ __forceinline__ void mma_tf32(float* d, const uint32_t* a, const uint32_t* b)
{
    asm volatile(
        "mma.sync.aligned.m16n8k8.row.col.f32.tf32.tf32.f32 "
        "{%0,%1,%2,%3}, {%4,%5,%6,%7}, {%8,%9}, {%0,%1,%2,%3};\n"
        : "+f"(d[0]), "+f"(d[1]), "+f"(d[2]), "+f"(d[3])
        : "r"(a[0]), "r"(a[1]), "r"(a[2]), "r"(a[3]),
          "r"(b[0]), "r"(b[1]));
}

__device__ __forceinline__ void ldsm_x4(uint32_t* r, uint32_t saddr)
{
    asm volatile(
        "ldmatrix.sync.aligned.m8n8.x4.shared.b16 {%0,%1,%2,%3}, [%4];\n"
        : "=r"(r[0]), "=r"(r[1]), "=r"(r[2]), "=r"(r[3])
        : "r"(saddr));
}

__device__ __forceinline__ void cp_async16(uint32_t dst, const void* src)
{
    asm volatile("cp.async.cg.shared.global [%0], [%1], 16;\n"
                 :: "r"(dst), "l"(src));
}
__device__ __forceinline__ void cp_commit()
{
    asm volatile("cp.async.commit_group;\n");
}
template<int N>
__device__ __forceinline__ void cp_wait()
{
    asm volatile("cp.async.wait_group %0;\n" :: "n"(N));
}

// ---------------- 3/5) tensor-core GEMM, 3xTF32, cp.async pipelined ---------
// out[b,m,n2] = sum_k W[m,k]*X[k,(b,n2)] + bias[m]; W original [M][K] layout.
// CONCAT: X rows [0,C1) from A1 (g_interp), rest from A2 (feat2).
// FUSE:   X element -> relu(x*scale[k]+shift[k]) applied at b-fragment read.
// Emits per-block per-channel {sum,sumsq} into bpart (fused BN stats).
template<int K, bool CONCAT, bool FUSE>
__global__ void __launch_bounds__(512, 2)
gemm_tc_kernel(const float* __restrict__ W, const float* __restrict__ bias,
               const float* __restrict__ A1, const float* __restrict__ A2,
               const float* __restrict__ scale, const float* __restrict__ shift,
               float* __restrict__ out, float2* __restrict__ bpart)
{
    extern __shared__ char sm[];
    const uint32_t smb = (uint32_t)__cvta_generic_to_shared(sm);
    const uint32_t wsm = smb + WOFF;
    const uint32_t xsm = smb + XOFF;
    float* s_sc = (float*)(sm + SCOFF);
    float* s_sh = (float*)(sm + SCOFF + 256*4);

    const int tid   = threadIdx.x;
    const int lane  = tid & 31;
    const int wid   = tid >> 5;         // 0..15
    const int g     = lane >> 2;
    const int tig   = lane & 3;
    const int mwarp = wid >> 1;         // 0..7 -> m base mwarp*32
    const int nwarp = wid & 1;          // 0..1 -> n base nwarp*32

    const int nglob = blockIdx.x * 64;
    const int b     = nglob >> 13;
    const int n2    = nglob & (N2 - 1);

    const float* A1b = A1 + (size_t)b * (CONCAT ? C1 : K) * N2 + n2;
    const float* A2b = CONCAT ? (A2 + (size_t)b * C2 * N2 + n2) : nullptr;

    if (FUSE && tid < K) {
        s_sc[tid] = scale[tid];
        s_sh[tid] = shift[tid];
    }

    float acc[2][4][4];
    #pragma unroll
    for (int mt = 0; mt < 2; ++mt)
        #pragma unroll
        for (int nt = 0; nt < 4; ++nt)
            #pragma unroll
            for (int r = 0; r < 4; ++r) acc[mt][nt][r] = 0.0f;

    // ldmatrix lane address within a W stage
    const int rowoff  = ((lane >> 3) & 1) * 8 + (lane & 7);
    const int wordoff = (lane >> 4) * 4;
    const uint32_t aOff = ((((mwarp*32 + rowoff) * 20) + wordoff) << 2);

    // loader task coords
    const int xkr = tid >> 4;           // X: k row (tid<256)
    const int xn4 = (tid & 15) * 4;     //    n quad

    auto load_stage = [&](int k0, int stg) {
        // W tile: 256 m x 16 k
        const uint32_t wdst = wsm + stg * W_STAGE;
        #pragma unroll
        for (int q = 0; q < 2; ++q) {
            const int t  = tid + q * 512;
            const int m  = t >> 2;
            const int kc = (t & 3) * 4;
            cp_async16(wdst + (((m * 20) + kc) << 2),
                       W + (size_t)m * K + k0 + kc);
        }
        // X tile: 16 k x 64 n
        if (tid < 256) {
            const int kg = k0 + xkr;
            const float* src;
            if (CONCAT)
                src = (kg < C1) ? (A1b + (size_t)kg * N2)
                                : (A2b + (size_t)(kg - C1) * N2);
            else
                src = A1b + (size_t)kg * N2;
            cp_async16(xsm + stg * X_STAGE + (((xkr * 72) + xn4) << 2),
                       src + xn4);
        }
    };

    constexpr int NITER = K / 16;
    #pragma unroll
    for (int p = 0; p < PSTAGES - 1; ++p) {
        load_stage(p * 16, p);
        cp_commit();
    }

    for (int i = 0; i < NITER; ++i) {
        const int inext = i + PSTAGES - 1;
        if (inext < NITER) load_stage(inext * 16, inext % PSTAGES);
        cp_commit();
        cp_wait<PSTAGES - 2>();
        __syncthreads();

        const int stg = i % PSTAGES;
        const uint32_t aBase = wsm + stg * W_STAGE + aOff;
        const float* Xs = (const float*)(sm + XOFF + stg * X_STAGE);
        const int k0 = i * 16;

        #pragma unroll
        for (int ks = 0; ks < 16; ks += 8) {
            float sc0, sh0, sc1, sh1;
            if (FUSE) {
                sc0 = s_sc[k0 + ks + tig];     sh0 = s_sh[k0 + ks + tig];
                sc1 = s_sc[k0 + ks + tig + 4]; sh1 = s_sh[k0 + ks + tig + 4];
            }
            #pragma unroll
            for (int mt = 0; mt < 2; ++mt) {
                uint32_t ah[4], al[4];
                ldsm_x4(ah, aBase + ((mt * 16 * 20 + ks) << 2));
                #pragma unroll
                for (int j = 0; j < 4; ++j) {
                    const float a = __uint_as_float(ah[j]);
                    al[j] = __float_as_uint(a - tf32_trunc(a));
                }
                #pragma unroll
                for (int nt = 0; nt < 4; ++nt) {
                    const int nn = nwarp * 32 + nt * 8 + g;
                    float b0 = Xs[(ks + tig) * 72 + nn];
                    float b1 = Xs[(ks + tig + 4) * 72 + nn];
                    if (FUSE) {
                        b0 = fmaxf(fmaf(b0, sc0, sh0), 0.0f);
                        b1 = fmaxf(fmaf(b1, sc1, sh1), 0.0f);
                    }
                    uint32_t bh[2] = { __float_as_uint(b0), __float_as_uint(b1) };
                    uint32_t bl[2] = { __float_as_uint(b0 - tf32_trunc(b0)),
                                       __float_as_uint(b1 - tf32_trunc(b1)) };
                    mma_tf32(acc[mt][nt], ah, bh);   // hi*hi
                    mma_tf32(acc[mt][nt], ah, bl);   // hi*lo
                    mma_tf32(acc[mt][nt], al, bh);   // lo*hi
                }
            }
        }
        __syncthreads();
    }

    // ---- epilogue: bias add, store, fused per-channel stats ----
    float* part = (float*)sm;   // reuse W stage 0: [nwarp][256][{s,ss}]
    float* ob = out + (size_t)b * MOUT * N2 + n2;
    #pragma unroll
    for (int mt = 0; mt < 2; ++mt) {
        #pragma unroll
        for (int h = 0; h < 2; ++h) {
            const int m  = mwarp * 32 + mt * 16 + h * 8 + g;
            const float bv = bias[m];
            float s = 0.0f, ss = 0.0f;
            #pragma unroll
            for (int nt = 0; nt < 4; ++nt) {
                const float v0 = acc[mt][nt][h*2+0] + bv;
                const float v1 = acc[mt][nt][h*2+1] + bv;
                const int n = nwarp * 32 + nt * 8 + 2 * tig;
                *(float2*)(ob + (size_t)m * N2 + n) = make_float2(v0, v1);
                s  += v0 + v1;
                ss += v0*v0 + v1*v1;
            }
            s  += __shfl_xor_sync(0xffffffffu, s, 1);
            s  += __shfl_xor_sync(0xffffffffu, s, 2);
            ss += __shfl_xor_sync(0xffffffffu, ss, 1);
            ss += __shfl_xor_sync(0xffffffffu, ss, 2);
            if (tig == 0) {
                part[(nwarp * 256 + m) * 2 + 0] = s;
                part[(nwarp * 256 + m) * 2 + 1] = ss;
            }
        }
    }
    __syncthreads();
    if (tid < 256) {
        float2 r;
        r.x = part[tid * 2]     + part[(256 + tid) * 2];
        r.y = part[tid * 2 + 1] + part[(256 + tid) * 2 + 1];
        bpart[(size_t)blockIdx.x * MOUT + tid] = r;
    }
}

// ---------------- 4/6) stage-2 stats reduce ---------------------------------
__global__ void stats2_kernel(const float* __restrict__ gamma,
                              const float* __restrict__ beta,
                              float* __restrict__ scale,
                              float* __restrict__ shift)
{
    const int c = blockIdx.x;
    double s = 0.0, ss = 0.0;
    for (int j = threadIdx.x; j < NBLK; j += 256) {
        const float2 p = g_bpart[(size_t)j * MOUT + c];
        s  += (double)p.x;
        ss += (double)p.y;
    }
    __shared__ double rs[256], rss[256];
    rs[threadIdx.x] = s; rss[threadIdx.x] = ss;
    __syncthreads();
    for (int o = 128; o > 0; o >>= 1) {
        if (threadIdx.x < o) {
            rs[threadIdx.x]  += rs[threadIdx.x + o];
            rss[threadIdx.x] += rss[threadIdx.x + o];
        }
        __syncthreads();
    }
    if (threadIdx.x == 0) {
        const double mean = rs[0] / (double)NTOT;
        const double var  = rss[0] / (double)NTOT - mean * mean;
        const float istd  = (float)(1.0 / sqrt(var + 1e-3));
        const float sc    = gamma[c] * istd;
        scale[c] = sc;
        shift[c] = beta[c] - (float)mean * sc;
    }
}

// ---------------- 7) in-place BN+ReLU of layer-2 output ---------------------
__global__ void finalize_kernel(float* __restrict__ out)
{
    const size_t i4 = (size_t)blockIdx.x * blockDim.x + threadIdx.x;
    const int c = (int)((i4 >> 11) & 255);
    float4* p = (float4*)out + i4;
    float4 v = *p;
    const float sc = g_scale2[c], sh = g_shift2[c];
    v.x = fmaxf(fmaf(v.x, sc, sh), 0.0f);
    v.y = fmaxf(fmaf(v.y, sc, sh), 0.0f);
    v.z = fmaxf(fmaf(v.z, sc, sh), 0.0f);
    v.w = fmaxf(fmaf(v.w, sc, sh), 0.0f);
    *p = v;
}

// ---------------- launch ----------------------------------------------------
extern "C" void kernel_launch(void* const* d_in, const int* in_sizes, int n_in,
                              void* d_out, int out_size)
{
    const float* xyz2  = (const float*)d_in[0];
    const float* xyz1  = (const float*)d_in[1];
    const float* feat2 = (const float*)d_in[2];
    const float* feat1 = (const float*)d_in[3];
    const float* W1    = (const float*)d_in[4];
    const float* b1    = (const float*)d_in[5];
    const float* g1    = (const float*)d_in[6];
    const float* be1   = (const float*)d_in[7];
    const float* W2    = (const float*)d_in[8];
    const float* b2    = (const float*)d_in[9];
    const float* g2    = (const float*)d_in[10];
    const float* be2   = (const float*)d_in[11];
    float* out = (float*)d_out;

    float  *p_interp, *p_Y1, *p_s1, *p_sh1, *p_s2, *p_sh2;
    float2 *p_bpart;
    cudaGetSymbolAddress((void**)&p_interp, g_interp);
    cudaGetSymbolAddress((void**)&p_Y1,     g_Y1);
    cudaGetSymbolAddress((void**)&p_s1,     g_scale1);
    cudaGetSymbolAddress((void**)&p_sh1,    g_shift1);
    cudaGetSymbolAddress((void**)&p_s2,     g_scale2);
    cudaGetSymbolAddress((void**)&p_sh2,    g_shift2);
    cudaGetSymbolAddress((void**)&p_bpart,  g_bpart);

    static int attr_done = 0;
    if (!attr_done) {
        cudaFuncSetAttribute(gemm_tc_kernel<CIN, true, false>,
                             cudaFuncAttributeMaxDynamicSharedMemorySize, SMEM_DYN);
        cudaFuncSetAttribute(gemm_tc_kernel<MOUT, false, true>,
                             cudaFuncAttributeMaxDynamicSharedMemorySize, SMEM_DYN);
        attr_done = 1;
    }

    knn_kernel<<<dim3(N2/256, BB), 256>>>(xyz2, xyz1);
    interp_kernel<<<dim3(N2/256, BB), 256>>>(feat1);

    // layer 1: y1 = W1 @ [interp; feat2] + b1 (raw) + fused stats partials
    gemm_tc_kernel<CIN, true, false><<<NBLK, 512, SMEM_DYN>>>(
        W1, b1, p_interp, feat2, nullptr, nullptr, p_Y1, p_bpart);
    stats2_kernel<<<MOUT, 256>>>(g1, be1, p_s1, p_sh1);

    // layer 2: y2 = W2 @ relu(bn(y1)) + b2 -> d_out (raw) + fused stats
    gemm_tc_kernel<MOUT, false, true><<<NBLK, 512, SMEM_DYN>>>(
        W2, b2, p_Y1, nullptr, p_s1, p_sh1, out, p_bpart);
    stats2_kernel<<<MOUT, 256>>>(g2, be2, p_s2, p_sh2);

    finalize_kernel<<<(NTOT * MOUT / 4) / 256, 256>>>(out);
}